// round 10
// baseline (speedup 1.0000x reference)
#include <cuda_runtime.h>
#include <cuda_fp16.h>
#include <cstdint>

#define H 8
#define B 4
#define S 2048
#define D 8
#define F 64
#define HB 32
#define TILES 64
#define ROWS_CTA 32      // S / TILES
#define RPW 8            // rows per warp (4 warps)

typedef unsigned long long u64;

// Scratch (static __device__, no allocation). q/v fp32, k fp16; all [hb][d][s].
__device__ float  g_q  [HB * D * S];        // pre-scaled by log2e/sqrt(8)
__device__ __half g_kTh[HB * D * S];        // k in fp16
__device__ float  g_vT [HB * D * S];
__device__ float  g_cs [HB * TILES * S];    // per-(hb,tile) colsum of normalized w
__device__ float  g_part[HB * D];           // per-hb head sums

__device__ __forceinline__ float ex2f(float x) {
    float y; asm("ex2.approx.ftz.f32 %0, %1;" : "=f"(y) : "f"(x)); return y;
}
__device__ __forceinline__ float rcpf(float x) {
    float y; asm("rcp.approx.ftz.f32 %0, %1;" : "=f"(y) : "f"(x)); return y;
}
__device__ __forceinline__ u64 fma2(u64 a, u64 b, u64 c) {
    u64 d; asm("fma.rn.f32x2 %0, %1, %2, %3;" : "=l"(d) : "l"(a), "l"(b), "l"(c)); return d;
}
__device__ __forceinline__ u64 mul2u(u64 a, u64 b) {
    u64 d; asm("mul.rn.f32x2 %0, %1, %2;" : "=l"(d) : "l"(a), "l"(b)); return d;
}
__device__ __forceinline__ u64 add2u(u64 a, u64 b) {
    u64 d; asm("add.rn.f32x2 %0, %1, %2;" : "=l"(d) : "l"(a), "l"(b)); return d;
}
__device__ __forceinline__ u64 pack2(float lo, float hi) {
    u64 d; asm("mov.b64 %0, {%1, %2};" : "=l"(d) : "f"(lo), "f"(hi)); return d;
}
__device__ __forceinline__ float2 unpk2(u64 a) {
    float2 r; asm("mov.b64 {%0, %1}, %2;" : "=f"(r.x), "=f"(r.y) : "l"(a)); return r;
}

// ---------------------------------------------------------------------------
// Kernel 1: QKV projection (k written as fp16).
// ---------------------------------------------------------------------------
#define K1_ROWS 16
__global__ void __launch_bounds__(192) qkv_kernel(
    const float* __restrict__ x,
    const float* __restrict__ Wq,
    const float* __restrict__ Wk,
    const float* __restrict__ Wv)
{
    __shared__ float xs[K1_ROWS * 64];
    const int tid = threadIdx.x;
    const int rowbase = blockIdx.x * K1_ROWS;

    for (int i = tid; i < K1_ROWS * 64; i += 192)
        xs[i] = x[(size_t)rowbase * 64 + i];

    const int tensor = tid / 64;
    const int c = tid % 64;
    const int h = c >> 3, d = c & 7;
    const float* W = (tensor == 0) ? Wq : ((tensor == 1) ? Wk : Wv);

    float w[64];
#pragma unroll
    for (int f = 0; f < 64; ++f) w[f] = __ldg(&W[((size_t)h * 64 + f) * 8 + d]);

    __syncthreads();

    float acc[K1_ROWS];
#pragma unroll
    for (int r = 0; r < K1_ROWS; ++r) acc[r] = 0.f;

#pragma unroll
    for (int f4 = 0; f4 < 16; ++f4) {
#pragma unroll
        for (int r = 0; r < K1_ROWS; ++r) {
            float4 xv = *(const float4*)&xs[r * 64 + f4 * 4];
            acc[r] = fmaf(xv.x, w[4*f4+0], fmaf(xv.y, w[4*f4+1],
                     fmaf(xv.z, w[4*f4+2], fmaf(xv.w, w[4*f4+3], acc[r]))));
        }
    }

    const int b  = rowbase >> 11;
    const int s0 = rowbase & 2047;
    const int hb = h * 4 + b;
    const float QS = 0.51006975f;  // log2(e)/sqrt(8)
    if (tensor == 0) {
        float* dst = g_q + ((size_t)hb * 8 + d) * S + s0;
#pragma unroll
        for (int i = 0; i < K1_ROWS / 4; ++i)
            *(float4*)(dst + 4 * i) = make_float4(acc[4*i]*QS, acc[4*i+1]*QS,
                                                  acc[4*i+2]*QS, acc[4*i+3]*QS);
    } else if (tensor == 1) {
        __half* dst = g_kTh + ((size_t)hb * 8 + d) * S + s0;
#pragma unroll
        for (int i = 0; i < K1_ROWS / 4; ++i) {
            __half2 h01 = __floats2half2_rn(acc[4*i+0], acc[4*i+1]);
            __half2 h23 = __floats2half2_rn(acc[4*i+2], acc[4*i+3]);
            uint2 st; st.x = *(unsigned*)&h01; st.y = *(unsigned*)&h23;
            *(uint2*)(dst + 4 * i) = st;
        }
    } else {
        float* dst = g_vT + ((size_t)hb * 8 + d) * S + s0;
#pragma unroll
        for (int i = 0; i < K1_ROWS / 4; ++i)
            *(float4*)(dst + 4 * i) = make_float4(acc[4*i], acc[4*i+1],
                                                  acc[4*i+2], acc[4*i+3]);
    }
}

// ---------------------------------------------------------------------------
// Kernel 2: attention weights — round-9 structure, occupancy 4.
// Colsums accumulate in half2 (32 regs, not 64) so both passes fit under the
// 128-reg cap of __launch_bounds__(128, 4). k tile fp16 smem (32KB).
// Pass 1: 2 groups x 4 rows, 16 chunks, k in regs; exp2 row sums -> invS.
// Pass 2: 4 groups x 2 rows; recompute exp, scale, __stcs fp32 weights,
// colsum csh[32] half2; cross-warp colsum reduce reuses the k smem (fp32).
// ---------------------------------------------------------------------------
__global__ void __launch_bounds__(128, 4) attn_kernel(float* __restrict__ wout)
{
    extern __shared__ float sm[];
    __half* kSh  = (__half*)sm;          // 16384 halfs (32KB) [d][s]
    u64*    q2S  = (u64*)(sm + 8192);    // 32 rows x 8 d, packed {q,q} (2KB)
    float*  invS = sm + 8192 + 512;      // 32 floats

    const int tid  = threadIdx.x;
    const int lane = tid & 31;
    const int wrp  = tid >> 5;
    const int tile = blockIdx.x;
    const int hb   = blockIdx.y;

    {
        const uint4* k4 = (const uint4*)(g_kTh + (size_t)hb * D * S);
        uint4* kd = (uint4*)kSh;
#pragma unroll
        for (int i = 0; i < 16; ++i) kd[tid + 128 * i] = k4[tid + 128 * i];
#pragma unroll
        for (int i = tid; i < 256; i += 128) {
            const int r = i >> 3, d = i & 7;
            float q = g_q[((size_t)hb * 8 + d) * S + tile * ROWS_CTA + r];
            q2S[i] = pack2(q, q);
        }
    }
    __syncthreads();

    const int r0 = wrp * RPW;

    // ---------------- pass 1: exp row sums (4-row groups) ------------------
#pragma unroll 1
    for (int g = 0; g < 2; ++g) {
        const int rl = r0 + g * 4;
        u64 q2[4][8];
#pragma unroll
        for (int r = 0; r < 4; ++r)
#pragma unroll
            for (int j = 0; j < 4; ++j) {
                ulonglong2 t = *(const ulonglong2*)(q2S + (rl + r) * 8 + j * 2);
                q2[r][2*j] = t.x; q2[r][2*j+1] = t.y;
            }
        float ls[4] = {0.f, 0.f, 0.f, 0.f};

#pragma unroll 1
        for (int c = 0; c < 16; ++c) {
            const int col = c * 128 + lane * 4;
            u64 ka[8], kb[8];
#pragma unroll
            for (int d = 0; d < 8; ++d) {
                uint2 raw = *(const uint2*)(kSh + d * S + col);     // LDS.64
                float2 f01 = __half22float2(*(__half2*)&raw.x);
                float2 f23 = __half22float2(*(__half2*)&raw.y);
                ka[d] = pack2(f01.x, f01.y);
                kb[d] = pack2(f23.x, f23.y);
            }
#pragma unroll
            for (int r = 0; r < 4; ++r) {
                u64 sa = mul2u(q2[r][0], ka[0]);
                u64 sb = mul2u(q2[r][1], ka[1]);
                sa = fma2(q2[r][2], ka[2], sa); sb = fma2(q2[r][3], ka[3], sb);
                sa = fma2(q2[r][4], ka[4], sa); sb = fma2(q2[r][5], ka[5], sb);
                sa = fma2(q2[r][6], ka[6], sa); sb = fma2(q2[r][7], ka[7], sb);
                float2 s1 = unpk2(add2u(sa, sb));
                u64 ta = mul2u(q2[r][0], kb[0]);
                u64 tb = mul2u(q2[r][1], kb[1]);
                ta = fma2(q2[r][2], kb[2], ta); tb = fma2(q2[r][3], kb[3], tb);
                ta = fma2(q2[r][4], kb[4], ta); tb = fma2(q2[r][5], kb[5], tb);
                ta = fma2(q2[r][6], kb[6], ta); tb = fma2(q2[r][7], kb[7], tb);
                float2 s2 = unpk2(add2u(ta, tb));
                ls[r] += (ex2f(s1.x) + ex2f(s1.y)) + (ex2f(s2.x) + ex2f(s2.y));
            }
        }

#pragma unroll
        for (int r = 0; r < 4; ++r) {
            float v = ls[r];
#pragma unroll
            for (int o = 16; o > 0; o >>= 1) v += __shfl_xor_sync(0xffffffffu, v, o);
            if (lane == r) invS[rl + r] = rcpf(v);
        }
    }
    __syncthreads();

    // ---------------- pass 2: recompute, normalize, write, colsum ----------
    __half2 csh[32];
#pragma unroll
    for (int i = 0; i < 32; ++i) csh[i] = __half2half2(__ushort_as_half(0));

#pragma unroll 1
    for (int g = 0; g < 4; ++g) {
        const int rl = r0 + g * 2;
        u64 q2[2][8];
        u64 iv2[2];
#pragma unroll
        for (int r = 0; r < 2; ++r) {
#pragma unroll
            for (int j = 0; j < 4; ++j) {
                ulonglong2 t = *(const ulonglong2*)(q2S + (rl + r) * 8 + j * 2);
                q2[r][2*j] = t.x; q2[r][2*j+1] = t.y;
            }
            float iv = invS[rl + r];
            iv2[r] = pack2(iv, iv);
        }
        const size_t wb = ((size_t)hb * S + (size_t)tile * ROWS_CTA + rl) * S;

#pragma unroll 1
        for (int c = 0; c < 16; ++c) {
            const int col = c * 128 + lane * 4;
            u64 ka[8], kb[8];
#pragma unroll
            for (int d = 0; d < 8; ++d) {
                uint2 raw = *(const uint2*)(kSh + d * S + col);
                float2 f01 = __half22float2(*(__half2*)&raw.x);
                float2 f23 = __half22float2(*(__half2*)&raw.y);
                ka[d] = pack2(f01.x, f01.y);
                kb[d] = pack2(f23.x, f23.y);
            }
#pragma unroll
            for (int r = 0; r < 2; ++r) {
                u64 sa = mul2u(q2[r][0], ka[0]);
                u64 sb = mul2u(q2[r][1], ka[1]);
                sa = fma2(q2[r][2], ka[2], sa); sb = fma2(q2[r][3], ka[3], sb);
                sa = fma2(q2[r][4], ka[4], sa); sb = fma2(q2[r][5], ka[5], sb);
                sa = fma2(q2[r][6], ka[6], sa); sb = fma2(q2[r][7], ka[7], sb);
                float2 s1 = unpk2(add2u(sa, sb));
                u64 ta = mul2u(q2[r][0], kb[0]);
                u64 tb = mul2u(q2[r][1], kb[1]);
                ta = fma2(q2[r][2], kb[2], ta); tb = fma2(q2[r][3], kb[3], tb);
                ta = fma2(q2[r][4], kb[4], ta); tb = fma2(q2[r][5], kb[5], tb);
                ta = fma2(q2[r][6], kb[6], ta); tb = fma2(q2[r][7], kb[7], tb);
                float2 s2 = unpk2(add2u(ta, tb));

                u64 w0 = mul2u(pack2(ex2f(s1.x), ex2f(s1.y)), iv2[r]);
                u64 w1 = mul2u(pack2(ex2f(s2.x), ex2f(s2.y)), iv2[r]);
                float2 a = unpk2(w0);
                float2 b = unpk2(w1);
                csh[2*c+0] = __hadd2(csh[2*c+0], __floats2half2_rn(a.x, a.y));
                csh[2*c+1] = __hadd2(csh[2*c+1], __floats2half2_rn(b.x, b.y));
                __stcs((float4*)(wout + wb + (size_t)r * S + col),
                       make_float4(a.x, a.y, b.x, b.y));
            }
        }
    }

    // ---------------- cross-warp colsum reduction (reuse k smem, fp32) -----
    __syncthreads();
    float* csS = (float*)kSh;   // 4 warps x 2048 floats = 32KB, exact fit
    {
        float* csW = csS + wrp * S;
#pragma unroll
        for (int c = 0; c < 16; ++c) {
            const int col = c * 128 + lane * 4;
            float2 f0 = __half22float2(csh[2*c+0]);
            float2 f1 = __half22float2(csh[2*c+1]);
            *(float4*)(csW + col) = make_float4(f0.x, f0.y, f1.x, f1.y);
        }
    }
    __syncthreads();
    {
        float* dst = g_cs + ((size_t)hb * TILES + tile) * S;
        const int j0 = tid * 16;
#pragma unroll
        for (int jj = 0; jj < 4; ++jj) {
            float4 s = make_float4(0.f, 0.f, 0.f, 0.f);
#pragma unroll
            for (int w = 0; w < 4; ++w) {
                float4 t = *(const float4*)(csS + w * S + j0 + jj * 4);
                s.x += t.x; s.y += t.y; s.z += t.z; s.w += t.w;
            }
            *(float4*)(dst + j0 + jj * 4) = s;
        }
    }
}

// ---------------------------------------------------------------------------
// Kernel 3: per-hb: cs_total[t] = sum_tile g_cs; head_sum[d] = sum_t cs*v[d][t]
// ---------------------------------------------------------------------------
__global__ void __launch_bounds__(256) colsum_v_kernel()
{
    const int hb  = blockIdx.x;
    const int tid = threadIdx.x;
    const int lane = tid & 31, wrp = tid >> 5;
    const int t0 = tid * 8;

    float cs[8];
#pragma unroll
    for (int i = 0; i < 8; ++i) cs[i] = 0.f;
#pragma unroll 1
    for (int tl = 0; tl < TILES; ++tl) {
        const float* src = g_cs + ((size_t)hb * TILES + tl) * S + t0;
        float4 a = *(const float4*)(src);
        float4 b = *(const float4*)(src + 4);
        cs[0]+=a.x; cs[1]+=a.y; cs[2]+=a.z; cs[3]+=a.w;
        cs[4]+=b.x; cs[5]+=b.y; cs[6]+=b.z; cs[7]+=b.w;
    }

    float p[8];
#pragma unroll
    for (int d = 0; d < 8; ++d) {
        const float* vr = g_vT + ((size_t)hb * 8 + d) * S + t0;
        float4 a = *(const float4*)(vr);
        float4 b = *(const float4*)(vr + 4);
        p[d] = cs[0]*a.x + cs[1]*a.y + cs[2]*a.z + cs[3]*a.w
             + cs[4]*b.x + cs[5]*b.y + cs[6]*b.z + cs[7]*b.w;
    }

    __shared__ float red[8][8];
#pragma unroll
    for (int d = 0; d < 8; ++d) {
        float v = p[d];
#pragma unroll
        for (int o = 16; o > 0; o >>= 1) v += __shfl_xor_sync(0xffffffffu, v, o);
        p[d] = v;
    }
    if (lane == 0) {
#pragma unroll
        for (int d = 0; d < 8; ++d) red[wrp][d] = p[d];
    }
    __syncthreads();
    if (tid < 8) {
        float s = 0.f;
#pragma unroll
        for (int w = 0; w < 8; ++w) s += red[w][tid];
        g_part[hb * 8 + tid] = s;
    }
}

// ---------------------------------------------------------------------------
// Kernel 4: out[b][f] = sum_{h,d} head_sum[b][h*8+d] * Wo[h*8+d][f]
// ---------------------------------------------------------------------------
__global__ void __launch_bounds__(256) out_kernel(
    const float* __restrict__ Wo, float* __restrict__ out)
{
    __shared__ float hs[256];
    const int t = threadIdx.x;
    {
        const int b = t >> 6, j = t & 63;
        const int h = j >> 3, d = j & 7;
        hs[t] = g_part[(h * 4 + b) * 8 + d];
    }
    __syncthreads();
    const int b = t >> 6, f = t & 63;
    float a = 0.f;
#pragma unroll
    for (int j = 0; j < 64; ++j)
        a = fmaf(hs[b * 64 + j], Wo[j * 64 + f], a);
    out[b * 64 + f] = a;
}

// ---------------------------------------------------------------------------
extern "C" void kernel_launch(void* const* d_in, const int* in_sizes, int n_in,
                              void* d_out, int out_size)
{
    const float* x  = (const float*)d_in[0];
    const float* Wq = (const float*)d_in[1];
    const float* Wk = (const float*)d_in[2];
    const float* Wv = (const float*)d_in[3];
    const float* Wo = (const float*)d_in[4];
    float* out = (float*)d_out;

    const long long WELEMS = (long long)HB * S * S;  // 134217728
    float* wout = out;
    bool has_sum = false;
    if ((long long)out_size >= WELEMS + 256) {  // [sum(256) | weights]
        wout = out + 256;
        has_sum = true;
    }

    const int k2_smem = 8192 * 4 + 256 * 8 + 32 * 4;  // 34944
    cudaFuncSetAttribute(attn_kernel, cudaFuncAttributeMaxDynamicSharedMemorySize, k2_smem);

    qkv_kernel<<<(B * S) / K1_ROWS, 192>>>(x, Wq, Wk, Wv);
    attn_kernel<<<dim3(TILES, HB), 128, k2_smem>>>(wout);
    if (has_sum) {
        colsum_v_kernel<<<HB, 256>>>();
        out_kernel<<<1, 256>>>(Wo, out);
    }
}

// round 11
// speedup vs baseline: 1.1049x; 1.1049x over previous
#include <cuda_runtime.h>
#include <cuda_fp16.h>
#include <cstdint>

#define H 8
#define B 4
#define S 2048
#define D 8
#define F 64
#define HB 32
#define TILES 64
#define ROWS_CTA 32      // S / TILES
#define RPW 8            // rows per warp (4 warps)

typedef unsigned long long u64;

// Scratch (static __device__, no allocation). q/v fp32, k fp16; all [hb][d][s].
__device__ float  g_q  [HB * D * S];        // pre-scaled by log2e/sqrt(8)
__device__ __half g_kTh[HB * D * S];        // k in fp16
__device__ float  g_vT [HB * D * S];
__device__ float  g_cs [HB * TILES * S];    // per-(hb,tile) colsum of normalized w
__device__ float  g_part[HB * D];           // per-hb head sums

__device__ __forceinline__ float ex2f(float x) {
    float y; asm("ex2.approx.ftz.f32 %0, %1;" : "=f"(y) : "f"(x)); return y;
}
__device__ __forceinline__ float rcpf(float x) {
    float y; asm("rcp.approx.ftz.f32 %0, %1;" : "=f"(y) : "f"(x)); return y;
}
__device__ __forceinline__ u64 fma2(u64 a, u64 b, u64 c) {
    u64 d; asm("fma.rn.f32x2 %0, %1, %2, %3;" : "=l"(d) : "l"(a), "l"(b), "l"(c)); return d;
}
__device__ __forceinline__ u64 mul2u(u64 a, u64 b) {
    u64 d; asm("mul.rn.f32x2 %0, %1, %2;" : "=l"(d) : "l"(a), "l"(b)); return d;
}
__device__ __forceinline__ u64 add2u(u64 a, u64 b) {
    u64 d; asm("add.rn.f32x2 %0, %1, %2;" : "=l"(d) : "l"(a), "l"(b)); return d;
}
__device__ __forceinline__ u64 pack2(float lo, float hi) {
    u64 d; asm("mov.b64 %0, {%1, %2};" : "=l"(d) : "f"(lo), "f"(hi)); return d;
}
__device__ __forceinline__ float2 unpk2(u64 a) {
    float2 r; asm("mov.b64 {%0, %1}, %2;" : "=f"(r.x), "=f"(r.y) : "l"(a)); return r;
}

// ---------------------------------------------------------------------------
// Kernel 1: QKV projection (k written as fp16).
// ---------------------------------------------------------------------------
#define K1_ROWS 16
__global__ void __launch_bounds__(192) qkv_kernel(
    const float* __restrict__ x,
    const float* __restrict__ Wq,
    const float* __restrict__ Wk,
    const float* __restrict__ Wv)
{
    __shared__ float xs[K1_ROWS * 64];
    const int tid = threadIdx.x;
    const int rowbase = blockIdx.x * K1_ROWS;

    for (int i = tid; i < K1_ROWS * 64; i += 192)
        xs[i] = x[(size_t)rowbase * 64 + i];

    const int tensor = tid / 64;
    const int c = tid % 64;
    const int h = c >> 3, d = c & 7;
    const float* W = (tensor == 0) ? Wq : ((tensor == 1) ? Wk : Wv);

    float w[64];
#pragma unroll
    for (int f = 0; f < 64; ++f) w[f] = __ldg(&W[((size_t)h * 64 + f) * 8 + d]);

    __syncthreads();

    float acc[K1_ROWS];
#pragma unroll
    for (int r = 0; r < K1_ROWS; ++r) acc[r] = 0.f;

#pragma unroll
    for (int f4 = 0; f4 < 16; ++f4) {
#pragma unroll
        for (int r = 0; r < K1_ROWS; ++r) {
            float4 xv = *(const float4*)&xs[r * 64 + f4 * 4];
            acc[r] = fmaf(xv.x, w[4*f4+0], fmaf(xv.y, w[4*f4+1],
                     fmaf(xv.z, w[4*f4+2], fmaf(xv.w, w[4*f4+3], acc[r]))));
        }
    }

    const int b  = rowbase >> 11;
    const int s0 = rowbase & 2047;
    const int hb = h * 4 + b;
    const float QS = 0.51006975f;  // log2(e)/sqrt(8)
    if (tensor == 0) {
        float* dst = g_q + ((size_t)hb * 8 + d) * S + s0;
#pragma unroll
        for (int i = 0; i < K1_ROWS / 4; ++i)
            *(float4*)(dst + 4 * i) = make_float4(acc[4*i]*QS, acc[4*i+1]*QS,
                                                  acc[4*i+2]*QS, acc[4*i+3]*QS);
    } else if (tensor == 1) {
        __half* dst = g_kTh + ((size_t)hb * 8 + d) * S + s0;
#pragma unroll
        for (int i = 0; i < K1_ROWS / 4; ++i) {
            __half2 h01 = __floats2half2_rn(acc[4*i+0], acc[4*i+1]);
            __half2 h23 = __floats2half2_rn(acc[4*i+2], acc[4*i+3]);
            uint2 st; st.x = *(unsigned*)&h01; st.y = *(unsigned*)&h23;
            *(uint2*)(dst + 4 * i) = st;
        }
    } else {
        float* dst = g_vT + ((size_t)hb * 8 + d) * S + s0;
#pragma unroll
        for (int i = 0; i < K1_ROWS / 4; ++i)
            *(float4*)(dst + 4 * i) = make_float4(acc[4*i], acc[4*i+1],
                                                  acc[4*i+2], acc[4*i+3]);
    }
}

// ---------------------------------------------------------------------------
// Kernel 2: attention weights — interleaved phases for uniform DRAM pressure.
// grid (TILES=64, HB=32), 128 threads, occ 3, k tile fp16 smem (32KB).
// Per warp, per 4-row group: (a) denominator sweep (16 chunks, k in regs,
// exp2 row sums, intra-warp shfl reduce -> inv in REGISTERS — no barrier,
// no smem), then immediately (b) recompute+normalize+store sweep for the
// same 4 rows (q2 reused from registers). Stores are spread across ~85% of
// kernel lifetime instead of a phase-aligned second half.
// Colsums accumulate in half2 (32 regs); cross-warp reduce reuses k smem.
// ---------------------------------------------------------------------------
__global__ void __launch_bounds__(128, 3) attn_kernel(float* __restrict__ wout)
{
    extern __shared__ float sm[];
    __half* kSh = (__half*)sm;          // 16384 halfs (32KB) [d][s]
    u64*    q2S = (u64*)(sm + 8192);    // 32 rows x 8 d, packed {q,q} (2KB)

    const int tid  = threadIdx.x;
    const int lane = tid & 31;
    const int wrp  = tid >> 5;
    const int tile = blockIdx.x;
    const int hb   = blockIdx.y;

    {
        const uint4* k4 = (const uint4*)(g_kTh + (size_t)hb * D * S);
        uint4* kd = (uint4*)kSh;
#pragma unroll
        for (int i = 0; i < 16; ++i) kd[tid + 128 * i] = k4[tid + 128 * i];
#pragma unroll
        for (int i = tid; i < 256; i += 128) {
            const int r = i >> 3, d = i & 7;
            float q = g_q[((size_t)hb * 8 + d) * S + tile * ROWS_CTA + r];
            q2S[i] = pack2(q, q);
        }
    }
    __syncthreads();

    const int r0 = wrp * RPW;

    __half2 csh[32];
#pragma unroll
    for (int i = 0; i < 32; ++i) csh[i] = __half2half2(__ushort_as_half(0));

#pragma unroll 1
    for (int g = 0; g < 2; ++g) {
        const int rl = r0 + g * 4;

        u64 q2[4][8];
#pragma unroll
        for (int r = 0; r < 4; ++r)
#pragma unroll
            for (int j = 0; j < 4; ++j) {
                ulonglong2 t = *(const ulonglong2*)(q2S + (rl + r) * 8 + j * 2);
                q2[r][2*j] = t.x; q2[r][2*j+1] = t.y;
            }

        // ---- (a) denominator sweep for these 4 rows ----
        float ls[4] = {0.f, 0.f, 0.f, 0.f};
#pragma unroll 1
        for (int c = 0; c < 16; ++c) {
            const int col = c * 128 + lane * 4;
            u64 ka[8], kb[8];
#pragma unroll
            for (int d = 0; d < 8; ++d) {
                uint2 raw = *(const uint2*)(kSh + d * S + col);     // LDS.64
                float2 f01 = __half22float2(*(__half2*)&raw.x);
                float2 f23 = __half22float2(*(__half2*)&raw.y);
                ka[d] = pack2(f01.x, f01.y);
                kb[d] = pack2(f23.x, f23.y);
            }
#pragma unroll
            for (int r = 0; r < 4; ++r) {
                u64 sa = mul2u(q2[r][0], ka[0]);
                u64 sb = mul2u(q2[r][1], ka[1]);
                sa = fma2(q2[r][2], ka[2], sa); sb = fma2(q2[r][3], ka[3], sb);
                sa = fma2(q2[r][4], ka[4], sa); sb = fma2(q2[r][5], ka[5], sb);
                sa = fma2(q2[r][6], ka[6], sa); sb = fma2(q2[r][7], ka[7], sb);
                float2 s1 = unpk2(add2u(sa, sb));
                u64 ta = mul2u(q2[r][0], kb[0]);
                u64 tb = mul2u(q2[r][1], kb[1]);
                ta = fma2(q2[r][2], kb[2], ta); tb = fma2(q2[r][3], kb[3], tb);
                ta = fma2(q2[r][4], kb[4], ta); tb = fma2(q2[r][5], kb[5], tb);
                ta = fma2(q2[r][6], kb[6], ta); tb = fma2(q2[r][7], kb[7], tb);
                float2 s2 = unpk2(add2u(ta, tb));
                ls[r] += (ex2f(s1.x) + ex2f(s1.y)) + (ex2f(s2.x) + ex2f(s2.y));
            }
        }

        u64 iv2[4];
#pragma unroll
        for (int r = 0; r < 4; ++r) {
            float v = ls[r];
#pragma unroll
            for (int o = 16; o > 0; o >>= 1) v += __shfl_xor_sync(0xffffffffu, v, o);
            float iv = rcpf(v);
            iv2[r] = pack2(iv, iv);
        }

        // ---- (b) recompute + normalize + store sweep (same 4 rows) ----
        const size_t wb = ((size_t)hb * S + (size_t)tile * ROWS_CTA + rl) * S;
#pragma unroll 1
        for (int c = 0; c < 16; ++c) {
            const int col = c * 128 + lane * 4;
            u64 ka[8], kb[8];
#pragma unroll
            for (int d = 0; d < 8; ++d) {
                uint2 raw = *(const uint2*)(kSh + d * S + col);
                float2 f01 = __half22float2(*(__half2*)&raw.x);
                float2 f23 = __half22float2(*(__half2*)&raw.y);
                ka[d] = pack2(f01.x, f01.y);
                kb[d] = pack2(f23.x, f23.y);
            }
#pragma unroll
            for (int r = 0; r < 4; ++r) {
                u64 sa = mul2u(q2[r][0], ka[0]);
                u64 sb = mul2u(q2[r][1], ka[1]);
                sa = fma2(q2[r][2], ka[2], sa); sb = fma2(q2[r][3], ka[3], sb);
                sa = fma2(q2[r][4], ka[4], sa); sb = fma2(q2[r][5], ka[5], sb);
                sa = fma2(q2[r][6], ka[6], sa); sb = fma2(q2[r][7], ka[7], sb);
                float2 s1 = unpk2(add2u(sa, sb));
                u64 ta = mul2u(q2[r][0], kb[0]);
                u64 tb = mul2u(q2[r][1], kb[1]);
                ta = fma2(q2[r][2], kb[2], ta); tb = fma2(q2[r][3], kb[3], tb);
                ta = fma2(q2[r][4], kb[4], ta); tb = fma2(q2[r][5], kb[5], tb);
                ta = fma2(q2[r][6], kb[6], ta); tb = fma2(q2[r][7], kb[7], tb);
                float2 s2 = unpk2(add2u(ta, tb));

                u64 w0 = mul2u(pack2(ex2f(s1.x), ex2f(s1.y)), iv2[r]);
                u64 w1 = mul2u(pack2(ex2f(s2.x), ex2f(s2.y)), iv2[r]);
                float2 a = unpk2(w0);
                float2 b = unpk2(w1);
                csh[2*c+0] = __hadd2(csh[2*c+0], __floats2half2_rn(a.x, a.y));
                csh[2*c+1] = __hadd2(csh[2*c+1], __floats2half2_rn(b.x, b.y));
                __stcs((float4*)(wout + wb + (size_t)r * S + col),
                       make_float4(a.x, a.y, b.x, b.y));
            }
        }
    }

    // ---------------- cross-warp colsum reduction (reuse k smem, fp32) -----
    __syncthreads();
    float* csS = (float*)kSh;   // 4 warps x 2048 floats = 32KB, exact fit
    {
        float* csW = csS + wrp * S;
#pragma unroll
        for (int c = 0; c < 16; ++c) {
            const int col = c * 128 + lane * 4;
            float2 f0 = __half22float2(csh[2*c+0]);
            float2 f1 = __half22float2(csh[2*c+1]);
            *(float4*)(csW + col) = make_float4(f0.x, f0.y, f1.x, f1.y);
        }
    }
    __syncthreads();
    {
        float* dst = g_cs + ((size_t)hb * TILES + tile) * S;
        const int j0 = tid * 16;
#pragma unroll
        for (int jj = 0; jj < 4; ++jj) {
            float4 s = make_float4(0.f, 0.f, 0.f, 0.f);
#pragma unroll
            for (int w = 0; w < 4; ++w) {
                float4 t = *(const float4*)(csS + w * S + j0 + jj * 4);
                s.x += t.x; s.y += t.y; s.z += t.z; s.w += t.w;
            }
            *(float4*)(dst + j0 + jj * 4) = s;
        }
    }
}

// ---------------------------------------------------------------------------
// Kernel 3: per-hb: cs_total[t] = sum_tile g_cs; head_sum[d] = sum_t cs*v[d][t]
// ---------------------------------------------------------------------------
__global__ void __launch_bounds__(256) colsum_v_kernel()
{
    const int hb  = blockIdx.x;
    const int tid = threadIdx.x;
    const int lane = tid & 31, wrp = tid >> 5;
    const int t0 = tid * 8;

    float cs[8];
#pragma unroll
    for (int i = 0; i < 8; ++i) cs[i] = 0.f;
#pragma unroll 1
    for (int tl = 0; tl < TILES; ++tl) {
        const float* src = g_cs + ((size_t)hb * TILES + tl) * S + t0;
        float4 a = *(const float4*)(src);
        float4 b = *(const float4*)(src + 4);
        cs[0]+=a.x; cs[1]+=a.y; cs[2]+=a.z; cs[3]+=a.w;
        cs[4]+=b.x; cs[5]+=b.y; cs[6]+=b.z; cs[7]+=b.w;
    }

    float p[8];
#pragma unroll
    for (int d = 0; d < 8; ++d) {
        const float* vr = g_vT + ((size_t)hb * 8 + d) * S + t0;
        float4 a = *(const float4*)(vr);
        float4 b = *(const float4*)(vr + 4);
        p[d] = cs[0]*a.x + cs[1]*a.y + cs[2]*a.z + cs[3]*a.w
             + cs[4]*b.x + cs[5]*b.y + cs[6]*b.z + cs[7]*b.w;
    }

    __shared__ float red[8][8];
#pragma unroll
    for (int d = 0; d < 8; ++d) {
        float v = p[d];
#pragma unroll
        for (int o = 16; o > 0; o >>= 1) v += __shfl_xor_sync(0xffffffffu, v, o);
        p[d] = v;
    }
    if (lane == 0) {
#pragma unroll
        for (int d = 0; d < 8; ++d) red[wrp][d] = p[d];
    }
    __syncthreads();
    if (tid < 8) {
        float s = 0.f;
#pragma unroll
        for (int w = 0; w < 8; ++w) s += red[w][tid];
        g_part[hb * 8 + tid] = s;
    }
}

// ---------------------------------------------------------------------------
// Kernel 4: out[b][f] = sum_{h,d} head_sum[b][h*8+d] * Wo[h*8+d][f]
// ---------------------------------------------------------------------------
__global__ void __launch_bounds__(256) out_kernel(
    const float* __restrict__ Wo, float* __restrict__ out)
{
    __shared__ float hs[256];
    const int t = threadIdx.x;
    {
        const int b = t >> 6, j = t & 63;
        const int h = j >> 3, d = j & 7;
        hs[t] = g_part[(h * 4 + b) * 8 + d];
    }
    __syncthreads();
    const int b = t >> 6, f = t & 63;
    float a = 0.f;
#pragma unroll
    for (int j = 0; j < 64; ++j)
        a = fmaf(hs[b * 64 + j], Wo[j * 64 + f], a);
    out[b * 64 + f] = a;
}

// ---------------------------------------------------------------------------
extern "C" void kernel_launch(void* const* d_in, const int* in_sizes, int n_in,
                              void* d_out, int out_size)
{
    const float* x  = (const float*)d_in[0];
    const float* Wq = (const float*)d_in[1];
    const float* Wk = (const float*)d_in[2];
    const float* Wv = (const float*)d_in[3];
    const float* Wo = (const float*)d_in[4];
    float* out = (float*)d_out;

    const long long WELEMS = (long long)HB * S * S;  // 134217728
    float* wout = out;
    bool has_sum = false;
    if ((long long)out_size >= WELEMS + 256) {  // [sum(256) | weights]
        wout = out + 256;
        has_sum = true;
    }

    const int k2_smem = 8192 * 4 + 256 * 8;  // 34816
    cudaFuncSetAttribute(attn_kernel, cudaFuncAttributeMaxDynamicSharedMemorySize, k2_smem);

    qkv_kernel<<<(B * S) / K1_ROWS, 192>>>(x, Wq, Wk, Wv);
    attn_kernel<<<dim3(TILES, HB), 128, k2_smem>>>(wout);
    if (has_sum) {
        colsum_v_kernel<<<HB, 256>>>();
        out_kernel<<<1, 256>>>(Wo, out);
    }
}